// round 16
// baseline (speedup 1.0000x reference)
#include <cuda_runtime.h>

typedef unsigned long long ull;

__device__ __forceinline__ float fast_tanh(float t) {
    float r;
    asm("tanh.approx.f32 %0, %1;" : "=f"(r) : "f"(t));
    return r;
}
__device__ __forceinline__ ull pack2(float lo, float hi) {
    ull r;
    asm("mov.b64 %0, {%1, %2};" : "=l"(r) : "f"(lo), "f"(hi));
    return r;
}
__device__ __forceinline__ ull splat2(float v) {
    ull r;
    asm("mov.b64 %0, {%1, %1};" : "=l"(r) : "f"(v));
    return r;
}
__device__ __forceinline__ void unpack2(ull v, float& lo, float& hi) {
    asm("mov.b64 {%0, %1}, %2;" : "=f"(lo), "=f"(hi) : "l"(v));
}
__device__ __forceinline__ ull ffma2(ull a, ull b, ull c) {
    ull d;
    asm("fma.rn.f32x2 %0, %1, %2, %3;" : "=l"(d) : "l"(a), "l"(b), "l"(c));
    return d;
}
__device__ __forceinline__ ull fadd2(ull a, ull b) {
    ull d;
    asm("add.rn.f32x2 %0, %1, %2;" : "=l"(d) : "l"(a), "l"(b));
    return d;
}

// All scalings folded; sigmoid-affine fused into FMA:
//   layer1: y_i = 0.5*c1_i*h_i  (tanh arg, weights pre-scaled)
//           g''_i = fma(y, tanh(y), y) = 2*y*sigmoid(c1*h)   [the 2 folded into w2]
//   layer2: v_j = 0.5*c2_j*z_j  (accumulated directly; bias in BOTH acc inits)
//           contribution = w3'' * fma(v, tanh(v), v),  w3'' = a2*W3/c2
struct Pr {
    ull w1a[4], w1b[4], b1[4];          // layer-1, pre-scaled by 0.5*c1 (packed over feature pairs)
    ull w2[4][4];                       // w2[j][q] lanes i=2q,2q+1: 0.5*c2_j*a1_i*W2[i][j]/c1_i
    ull vb[4];                          // pack(0.5*c2_j*b2_j, 0)  -- lane-sum yields bias once per row
    ull w3s[4];                         // splat(a2_j*W3_j/c2_j)
    ull b3s;                            // splat(b3)
};

// layer 1 for one row: produce g''[4] (8 features as 4 f32x2 pairs)
__device__ __forceinline__ void layer1(float x0, float x1, const Pr& p, ull g[4]) {
    ull x0p = splat2(x0), x1p = splat2(x1);
#pragma unroll
    for (int q = 0; q < 4; q++) {
        ull y = ffma2(x0p, p.w1a[q], ffma2(x1p, p.w1b[q], p.b1[q]));  // y = 0.5*c1*h
        float t0, t1; unpack2(y, t0, t1);
        ull tp = pack2(fast_tanh(t0), fast_tanh(t1));
        g[q] = ffma2(y, tp, y);                  // y*(1+tanh) = 2*y*sigma  (0.5 folded into w2)
    }
}

// epilogue for one row-pair: layer2 + layer3, packed over (rowA, rowB)
__device__ __forceinline__ float2 epilogue(const ull gA[4], const ull gB[4], const Pr& p) {
    ull op = p.b3s;                              // packed output accumulator (rowA, rowB)
#pragma unroll
    for (int j = 0; j < 4; j++) {
        ull accA = ffma2(gA[0], p.w2[j][0], p.vb[j]);   // bias folded into BOTH inits
        ull accB = ffma2(gB[0], p.w2[j][0], p.vb[j]);   // (lane-sum adds it exactly once per row)
#pragma unroll
        for (int q = 1; q < 4; q++) {
            accA = ffma2(gA[q], p.w2[j][q], accA);
            accB = ffma2(gB[q], p.w2[j][q], accB);
        }
        float alo, ahi, blo, bhi;
        unpack2(accA, alo, ahi);
        unpack2(accB, blo, bhi);
        ull vp = fadd2(pack2(alo, blo), pack2(ahi, bhi));   // v = 0.5*c2*z  (rowA, rowB)
        float t0, t1; unpack2(vp, t0, t1);
        ull tp = pack2(fast_tanh(t0), fast_tanh(t1));
        op = ffma2(ffma2(vp, tp, vp), p.w3s[j], op);  // o += w3'' * v*(1+tanh) = a2*W3*z*sigma
    }
    float oA, oB; unpack2(op, oA, oB);
    return make_float2(oA, oB);
}

__global__ __launch_bounds__(128, 8)   // cap 64 regs -> 8 blocks/SM
void moth_mlp_kernel(const float4* __restrict__ x4,
                     const float* __restrict__ W1, const float* __restrict__ b1,
                     const float* __restrict__ a1, const float* __restrict__ c1,
                     const float* __restrict__ W2, const float* __restrict__ b2,
                     const float* __restrict__ a2, const float* __restrict__ c2,
                     const float* __restrict__ W3, const float* __restrict__ b3,
                     float4* __restrict__ out4,
                     int npairs, int nrows)
{
    // Fold params ONCE PER BLOCK into shared (9 threads); main loop reads via
    // broadcast LDS. ptxas hoists the hot subset into registers under the cap.
    __shared__ Pr p;
    {
        int t = threadIdx.x;
        if (t < 4) {                      // q-sections of layer 1
            int q = t, i0 = 2*q, i1 = 2*q + 1;
            float s0 = 0.5f * c1[i0], s1 = 0.5f * c1[i1];
            p.w1a[q] = pack2(s0 * W1[i0],     s1 * W1[i1]);
            p.w1b[q] = pack2(s0 * W1[8 + i0], s1 * W1[8 + i1]);
            p.b1[q]  = pack2(s0 * b1[i0],     s1 * b1[i1]);
        } else if (t < 8) {               // j-sections of layers 2+3
            int j = t - 4;
            float c2j = c2[j];
#pragma unroll
            for (int q = 0; q < 4; q++) {
                int i0 = 2*q, i1 = 2*q + 1;
                p.w2[j][q] = pack2(0.5f * c2j * a1[i0] * W2[i0*4 + j] * __fdividef(1.f, c1[i0]),
                                   0.5f * c2j * a1[i1] * W2[i1*4 + j] * __fdividef(1.f, c1[i1]));
            }
            p.vb[j]  = pack2(0.5f * c2j * b2[j], 0.0f);
            p.w3s[j] = splat2(a2[j] * W3[j] * __fdividef(1.f, c2j));
        } else if (t == 8) {
            p.b3s = splat2(b3[0]);
        }
    }
    __syncthreads();

    const int stride = gridDim.x * blockDim.x;
    int tid = blockIdx.x * blockDim.x + threadIdx.x;

    int nquads = npairs >> 1;          // 2 pairs (4 rows) per iteration

    for (int qi = tid; qi < nquads; qi += stride) {
        // two independent float4 loads (front-batched -> MLP=2)
        float4 xA = x4[2*qi + 0];
        float4 xB = x4[2*qi + 1];

        // four independent layer-1 chains (16 tanh batched)
        ull g0[4], g1[4], g2[4], g3[4];
        layer1(xA.x, xA.y, p, g0);
        layer1(xA.z, xA.w, p, g1);
        layer1(xB.x, xB.y, p, g2);
        layer1(xB.z, xB.w, p, g3);

        // two independent epilogues; single STG.128 for 4 outputs
        float2 rA = epilogue(g0, g1, p);
        float2 rB = epilogue(g2, g3, p);

        out4[qi] = make_float4(rA.x, rA.y, rB.x, rB.y);
    }

    // leftover odd pair (not hit for B = 8388608, kept for safety)
    if ((npairs & 1) && tid == 0) {
        int pi = npairs - 1;
        float4 xx = x4[pi];
        ull gA[4], gB[4];
        layer1(xx.x, xx.y, p, gA);
        layer1(xx.z, xx.w, p, gB);
        float2 r = epilogue(gA, gB, p);
        reinterpret_cast<float2*>(out4)[pi] = r;
    }

    // odd-row tail (not hit for B = 8388608, kept for safety)
    if ((nrows & 1) && tid == 0) {
        const float2* x2 = reinterpret_cast<const float2*>(x4);
        float2 xr = x2[nrows - 1];
        ull gA[4], gB[4];
        layer1(xr.x, xr.y, p, gA);
        layer1(xr.x, xr.y, p, gB);
        float2 r = epilogue(gA, gB, p);
        reinterpret_cast<float*>(out4)[nrows - 1] = r.x;
    }
}

extern "C" void kernel_launch(void* const* d_in, const int* in_sizes, int n_in,
                              void* d_out, int out_size)
{
    const float4* x4 = (const float4*)d_in[0];
    const float* W1 = (const float*)d_in[1];
    const float* b1 = (const float*)d_in[2];
    const float* a1 = (const float*)d_in[3];
    const float* c1 = (const float*)d_in[4];
    const float* W2 = (const float*)d_in[5];
    const float* b2 = (const float*)d_in[6];
    const float* a2 = (const float*)d_in[7];
    const float* c2 = (const float*)d_in[8];
    const float* W3 = (const float*)d_in[9];
    const float* b3 = (const float*)d_in[10];

    int nrows = in_sizes[0] / 2;   // x is [B, 2]
    int npairs = nrows / 2;

    const int threads = 128;
    const int blocks = 1184;       // 148 SMs * 8 resident blocks: one clean wave

    moth_mlp_kernel<<<blocks, threads>>>(x4, W1, b1, a1, c1, W2, b2, a2, c2, W3, b3,
                                         (float4*)d_out, npairs, nrows);
}